// round 7
// baseline (speedup 1.0000x reference)
#include <cuda_runtime.h>
#include <cstdint>

#define T_STEPS 2048
#define HID 64
#define EPB 7
#define NTHR 512
#define QS (EPB * HID)            // 448

typedef unsigned long long u64;

// ---------- f32x2 packed math ----------
__device__ __forceinline__ u64 fma2(u64 a, u64 b, u64 c) {
    u64 d; asm("fma.rn.f32x2 %0, %1, %2, %3;" : "=l"(d) : "l"(a), "l"(b), "l"(c)); return d;
}
__device__ __forceinline__ u64 pack2(float lo, float hi) {
    u64 d; asm("mov.b64 %0, {%1, %2};" : "=l"(d) : "f"(lo), "f"(hi)); return d;
}
__device__ __forceinline__ float2 unpack2(u64 v) {
    float a, b; asm("mov.b64 {%0, %1}, %2;" : "=f"(a), "=f"(b) : "l"(v));
    return make_float2(a, b);
}

// ---------- exact-ish activations (EX2+RCP; 1.7e-6 end-to-end proven) ----------
__device__ __forceinline__ float sig_(float x) {
    return __fdividef(1.0f, 1.0f + __expf(-x));
}
__device__ __forceinline__ float tanhx_(float x) {
    float e = __expf(2.0f * fabsf(x));
    float t = 1.0f - __fdividef(2.0f, e + 1.0f);
    return copysignf(t, x);
}

extern __shared__ float smem_f[];
// SMEM layout (float offsets)
#define OX   0                          // x: [EPB][T_STEPS]
#define OH1  (EPB * T_STEPS)            // h1: [2][QS]
#define OH2  (OH1 + 2 * QS)             // h2: [QS]
#define OP0  (OH2 + QS)                 // psh0: [8][EPB][HID] float2
#define OP1  (OP0 + 2 * 8 * QS)
#define OB0  (OP1 + 2 * 8 * QS)
#define OB1  (OB0 + 4 * HID)
#define OXW  (OB1 + 4 * HID)
#define SMEM_FLOATS (OXW + 4 * HID)     // 30784 floats = 123136 B

__global__ void __launch_bounds__(NTHR, 1)
lstm_fused(const float* __restrict__ x,
           const float* __restrict__ Wih0, const float* __restrict__ Whh0,
           const float* __restrict__ bih0, const float* __restrict__ bhh0,
           const float* __restrict__ Wih1, const float* __restrict__ Whh1,
           const float* __restrict__ bih1, const float* __restrict__ bhh1,
           const float* __restrict__ fcW,  const float* __restrict__ fcb,
           float* __restrict__ out, int B)
{
    float*  xs   = smem_f + OX;
    float*  h1f  = smem_f + OH1;
    float*  h2f  = smem_f + OH2;
    float2* psh0 = (float2*)(smem_f + OP0);
    float2* psh1 = (float2*)(smem_f + OP1);
    float4* b0s  = (float4*)(smem_f + OB0);
    float4* b1s  = (float4*)(smem_f + OB1);
    float4* xws  = (float4*)(smem_f + OXW);

    const int tid = threadIdx.x;
    const int u   = tid & 63;
    const int gp  = (tid >> 6) & 1;
    const int s   = tid >> 7;
    const int q   = s * 2 + gp;            // 0..7
    const int b0e = blockIdx.x * EPB;

    // ---- stage x ----
    for (int i = tid; i < EPB * T_STEPS / 4; i += NTHR) {
        int e = i / (T_STEPS / 4), c = i % (T_STEPS / 4);
        int be = b0e + e; if (be > B - 1) be = B - 1;
        ((float4*)xs)[i] = ((const float4*)(x + (size_t)be * T_STEPS))[c];
    }
    if (tid < HID) {
        b0s[tid] = make_float4(bih0[tid]       + bhh0[tid],
                               bih0[64 + tid]  + bhh0[64 + tid],
                               bih0[128 + tid] + bhh0[128 + tid],
                               bih0[192 + tid] + bhh0[192 + tid]);
        b1s[tid] = make_float4(bih1[tid]       + bhh1[tid],
                               bih1[64 + tid]  + bhh1[64 + tid],
                               bih1[128 + tid] + bhh1[128 + tid],
                               bih1[192 + tid] + bhh1[192 + tid]);
        xws[tid] = make_float4(Wih0[tid], Wih0[64 + tid],
                               Wih0[128 + tid], Wih0[192 + tid]);
    }
    for (int i = tid; i < 3 * QS; i += NTHR) h1f[i] = 0.0f;   // h1 both slots + h2
    for (int i = tid; i < 8 * QS; i += NTHR)                  // psh0 = L0-partials(0) = 0
        psh0[i] = make_float2(0.0f, 0.0f);

    // ---- register weights (k-pair packed; thread handles gates rA,rB) ----
    const int rA = (gp * 2) * 64 + u, rB = (gp * 2 + 1) * 64 + u;
    u64 w0A[8], w0B[8];
    {
        const int k0 = s * 16;
#pragma unroll
        for (int p = 0; p < 8; ++p) {
            w0A[p] = pack2(Whh0[rA * 64 + k0 + 2 * p], Whh0[rA * 64 + k0 + 2 * p + 1]);
            w0B[p] = pack2(Whh0[rB * 64 + k0 + 2 * p], Whh0[rB * 64 + k0 + 2 * p + 1]);
        }
    }
    u64 w1A[16], w1B[16];
    {
        const float* Wsrc = (s < 2) ? Wih1 : Whh1;
        const int kb = (s & 1) * 32;
#pragma unroll
        for (int p = 0; p < 16; ++p) {
            w1A[p] = pack2(Wsrc[rA * 64 + kb + 2 * p], Wsrc[rA * 64 + kb + 2 * p + 1]);
            w1B[p] = pack2(Wsrc[rB * 64 + kb + 2 * p], Wsrc[rB * 64 + kb + 2 * p + 1]);
        }
    }

    // phase-1 writer bases
    float2* pw0 = psh0 + (q * EPB) * HID + u;
    float2* pw1 = psh1 + (q * EPB) * HID + u;
    // phase-2 (activation) state: threads q<7 own cell (e=q, u) for both layers
    const bool act = (q < 7);
    const int  e0  = act ? q : 0;
    const float2* pr0 = psh0 + e0 * HID + u;
    const float2* pr1 = psh1 + e0 * HID + u;
    float*        hw1 = h1f + e0 * HID + u;     // + parity*QS
    float*        hw2 = h2f + e0 * HID + u;
    const float*  xb  = xs + e0 * T_STEPS;
    const float4* bp0 = b0s + u;
    const float4* bp1 = b1s + u;
    const float4* xwp = xws + u;

    float cL0 = 0.0f, cL1 = 0.0f;
    __syncthreads();

#pragma unroll 1
    for (int j = 0; j <= T_STEPS; ++j) {
        const int pj = j & 1;              // parity of h1[j]

        // ================= region P =================
        // (a) L0 activation for step j  (MUFU issues early, drains under fma)
        float h1new = 0.0f; bool st1 = act && (j < T_STEPS);
        if (st1) {
            float2 a0 = pr0[0 * QS], a1 = pr0[2 * QS], a2 = pr0[4 * QS], a3 = pr0[6 * QS];
            float2 g0 = pr0[1 * QS], g1 = pr0[3 * QS], g2 = pr0[5 * QS], g3 = pr0[7 * QS];
            float4 bb = *bp0; float4 xw = *xwp;
            float xv = xb[j];
            float pi = a0.x + a1.x + a2.x + a3.x + bb.x + xv * xw.x;
            float pf = a0.y + a1.y + a2.y + a3.y + bb.y + xv * xw.y;
            float pg = g0.x + g1.x + g2.x + g3.x + bb.z + xv * xw.z;
            float po = g0.y + g1.y + g2.y + g3.y + bb.w + xv * xw.w;
            float gi = sig_(pi), gf = sig_(pf), gg = tanhx_(pg), go = sig_(po);
            cL0 = gf * cL0 + gi * gg;
            h1new = go * tanhx_(cL0);
        }
        // (b) L1 partials for step j-1: reads h1[j-1], h2[j-2]
        if (j > 0) {
            const ulonglong2* hp = (s < 2)
                ? (const ulonglong2*)(h1f + (pj ^ 1) * QS) + s * 8
                : (const ulonglong2*)h2f + (s - 2) * 8;
#pragma unroll
            for (int e = 0; e < EPB; ++e) {
                u64 aA = 0, aB = 0;
#pragma unroll
                for (int p = 0; p < 8; ++p) {
                    ulonglong2 v = hp[e * 16 + p];
                    aA = fma2(v.x, w1A[2 * p], aA);     aB = fma2(v.x, w1B[2 * p], aB);
                    aA = fma2(v.y, w1A[2 * p + 1], aA); aB = fma2(v.y, w1B[2 * p + 1], aB);
                }
                float2 fa = unpack2(aA), fb = unpack2(aB);
                pw1[e * HID] = make_float2(fa.x + fa.y, fb.x + fb.y);
            }
        }
        if (st1) hw1[pj * QS] = h1new;
        __syncthreads();

        // ================= region Q =================
        // (a) L1 activation for step j-1
        float h2new = 0.0f; bool st2 = act && (j > 0);
        if (st2) {
            float2 a0 = pr1[0 * QS], a1 = pr1[2 * QS], a2 = pr1[4 * QS], a3 = pr1[6 * QS];
            float2 g0 = pr1[1 * QS], g1 = pr1[3 * QS], g2 = pr1[5 * QS], g3 = pr1[7 * QS];
            float4 bb = *bp1;
            float pi = a0.x + a1.x + a2.x + a3.x + bb.x;
            float pf = a0.y + a1.y + a2.y + a3.y + bb.y;
            float pg = g0.x + g1.x + g2.x + g3.x + bb.z;
            float po = g0.y + g1.y + g2.y + g3.y + bb.w;
            float gi = sig_(pi), gf = sig_(pf), gg = tanhx_(pg), go = sig_(po);
            cL1 = gf * cL1 + gi * gg;
            h2new = go * tanhx_(cL1);
        }
        // (b) L0 partials for step j+1: reads h1[j]  (valid while j+1 <= T-1)
        if (j < T_STEPS - 1) {
            const ulonglong2* hp = (const ulonglong2*)(h1f + pj * QS) + s * 4;
#pragma unroll
            for (int e = 0; e < EPB; ++e) {
                ulonglong2 v0 = hp[e * 16 + 0], v1 = hp[e * 16 + 1];
                ulonglong2 v2 = hp[e * 16 + 2], v3 = hp[e * 16 + 3];
                u64 aA = 0, aB = 0;
                aA = fma2(v0.x, w0A[0], aA); aB = fma2(v0.x, w0B[0], aB);
                aA = fma2(v0.y, w0A[1], aA); aB = fma2(v0.y, w0B[1], aB);
                aA = fma2(v1.x, w0A[2], aA); aB = fma2(v1.x, w0B[2], aB);
                aA = fma2(v1.y, w0A[3], aA); aB = fma2(v1.y, w0B[3], aB);
                aA = fma2(v2.x, w0A[4], aA); aB = fma2(v2.x, w0B[4], aB);
                aA = fma2(v2.y, w0A[5], aA); aB = fma2(v2.y, w0B[5], aB);
                aA = fma2(v3.x, w0A[6], aA); aB = fma2(v3.x, w0B[6], aB);
                aA = fma2(v3.y, w0A[7], aA); aB = fma2(v3.y, w0B[7], aB);
                float2 fa = unpack2(aA), fb = unpack2(aB);
                pw0[e * HID] = make_float2(fa.x + fa.y, fb.x + fb.y);
            }
        }
        if (st2) hw2[0] = h2new;
        __syncthreads();
    }

    // ---- final FC: h2f holds h2[T-1] ----
    if (tid < EPB * 32) {
        const int e = tid >> 5, lane = tid & 31;
        const float* h2l = h2f + e * HID;
        float acc = h2l[lane] * fcW[lane] + h2l[32 + lane] * fcW[32 + lane];
#pragma unroll
        for (int o = 16; o > 0; o >>= 1)
            acc += __shfl_down_sync(0xFFFFFFFFu, acc, o);
        if (lane == 0) {
            int be = b0e + e; if (be > B - 1) be = B - 1;
            out[be] = acc + fcb[0];
        }
    }
}

extern "C" void kernel_launch(void* const* d_in, const int* in_sizes, int n_in,
                              void* d_out, int out_size)
{
    const float* x    = (const float*)d_in[0];
    const float* Wih0 = (const float*)d_in[1];
    const float* Whh0 = (const float*)d_in[2];
    const float* bih0 = (const float*)d_in[3];
    const float* bhh0 = (const float*)d_in[4];
    const float* Wih1 = (const float*)d_in[5];
    const float* Whh1 = (const float*)d_in[6];
    const float* bih1 = (const float*)d_in[7];
    const float* bhh1 = (const float*)d_in[8];
    const float* fcW  = (const float*)d_in[9];
    const float* fcb  = (const float*)d_in[10];
    float* out = (float*)d_out;

    int B = in_sizes[0] / T_STEPS;
    if (B < 1) B = 1;
    int blocks = (B + EPB - 1) / EPB;

    const int smem_bytes = SMEM_FLOATS * 4;
    cudaFuncSetAttribute(lstm_fused, cudaFuncAttributeMaxDynamicSharedMemorySize,
                         smem_bytes);

    lstm_fused<<<blocks, NTHR, smem_bytes>>>(x, Wih0, Whh0, bih0, bhh0,
                                             Wih1, Whh1, bih1, bhh1,
                                             fcW, fcb, out, B);
}

// round 8
// speedup vs baseline: 1.1903x; 1.1903x over previous
#include <cuda_runtime.h>
#include <cstdint>

#define T_STEPS 2048
#define HID 64
#define EPB 7
#define NTHR 512

typedef unsigned long long u64;

// ---------- f32x2 packed math ----------
__device__ __forceinline__ u64 fma2(u64 a, u64 b, u64 c) {
    u64 d; asm("fma.rn.f32x2 %0, %1, %2, %3;" : "=l"(d) : "l"(a), "l"(b), "l"(c)); return d;
}
__device__ __forceinline__ u64 pack2(float lo, float hi) {
    u64 d; asm("mov.b64 %0, {%1, %2};" : "=l"(d) : "f"(lo), "f"(hi)); return d;
}
__device__ __forceinline__ float2 unpack2(u64 v) {
    float a, b; asm("mov.b64 {%0, %1}, %2;" : "=f"(a), "=f"(b) : "l"(v));
    return make_float2(a, b);
}

// ---------- fast activations: MUFU.TANH (1 MUFU per tanh) ----------
__device__ __forceinline__ float tanh_fast(float x) {
    float r; asm("tanh.approx.f32 %0, %1;" : "=f"(r) : "f"(x)); return r;
}
__device__ __forceinline__ float sig_fast(float x) {
    return fmaf(tanh_fast(0.5f * x), 0.5f, 0.5f);
}

extern __shared__ float smem_f[];

// SMEM layout (float offsets)
#define OX   0
#define OH1  (EPB * T_STEPS)                 // 14336
#define OH2  (OH1 + 2 * EPB * HID)           // +896
#define OP0  (OH2 + 2 * EPB * HID)           // psh0: [8][EPB][HID] float2
#define OP1  (OP0 + 2 * 8 * EPB * HID)
#define OB0  (OP1 + 2 * 8 * EPB * HID)
#define OB1  (OB0 + 4 * HID)
#define OXW  (OB1 + 4 * HID)
#define SMEM_FLOATS (OXW + 4 * HID)          // 31232 floats = 124928 B

__global__ void __launch_bounds__(NTHR, 1)
lstm_fused(const float* __restrict__ x,
           const float* __restrict__ Wih0, const float* __restrict__ Whh0,
           const float* __restrict__ bih0, const float* __restrict__ bhh0,
           const float* __restrict__ Wih1, const float* __restrict__ Whh1,
           const float* __restrict__ bih1, const float* __restrict__ bhh1,
           const float* __restrict__ fcW,  const float* __restrict__ fcb,
           float* __restrict__ out, int B)
{
    float*  xs   = smem_f + OX;
    float*  h1f  = smem_f + OH1;
    float*  h2f  = smem_f + OH2;
    float2* psh0 = (float2*)(smem_f + OP0);
    float2* psh1 = (float2*)(smem_f + OP1);
    float4* b0s  = (float4*)(smem_f + OB0);
    float4* b1s  = (float4*)(smem_f + OB1);
    float4* xws  = (float4*)(smem_f + OXW);

    const int tid = threadIdx.x;
    const int u   = tid & 63;
    const int gp  = (tid >> 6) & 1;
    const int s   = tid >> 7;
    const int q   = s * 2 + gp;          // 0..7
    const int b0e = blockIdx.x * EPB;

    // ---- stage x rows ----
    for (int i = tid; i < EPB * T_STEPS / 4; i += NTHR) {
        int e = i / (T_STEPS / 4), c = i % (T_STEPS / 4);
        int be = b0e + e; if (be > B - 1) be = B - 1;
        ((float4*)xs)[i] = ((const float4*)(x + (size_t)be * T_STEPS))[c];
    }
    if (tid < HID) {
        b0s[tid] = make_float4(bih0[tid]       + bhh0[tid],
                               bih0[64 + tid]  + bhh0[64 + tid],
                               bih0[128 + tid] + bhh0[128 + tid],
                               bih0[192 + tid] + bhh0[192 + tid]);
        b1s[tid] = make_float4(bih1[tid]       + bhh1[tid],
                               bih1[64 + tid]  + bhh1[64 + tid],
                               bih1[128 + tid] + bhh1[128 + tid],
                               bih1[192 + tid] + bhh1[192 + tid]);
        xws[tid] = make_float4(Wih0[tid], Wih0[64 + tid],
                               Wih0[128 + tid], Wih0[192 + tid]);
    }
    for (int i = tid; i < 2 * EPB * HID; i += NTHR) { h1f[i] = 0.0f; h2f[i] = 0.0f; }

    // ---- register weights (k-pair packed f32x2) ----
    const int rA = (gp * 2) * 64 + u, rB = (gp * 2 + 1) * 64 + u;
    u64 w0A[8], w0B[8];
    {
        const int k0 = s * 16;
#pragma unroll
        for (int p = 0; p < 8; ++p) {
            w0A[p] = pack2(Whh0[rA * 64 + k0 + 2 * p], Whh0[rA * 64 + k0 + 2 * p + 1]);
            w0B[p] = pack2(Whh0[rB * 64 + k0 + 2 * p], Whh0[rB * 64 + k0 + 2 * p + 1]);
        }
    }
    u64 w1A[16], w1B[16];
    {
        const float* Wsrc = (s < 2) ? Wih1 : Whh1;
        const int kb = (s & 1) * 32;
#pragma unroll
        for (int p = 0; p < 16; ++p) {
            w1A[p] = pack2(Wsrc[rA * 64 + kb + 2 * p], Wsrc[rA * 64 + kb + 2 * p + 1]);
            w1B[p] = pack2(Wsrc[rB * 64 + kb + 2 * p], Wsrc[rB * 64 + kb + 2 * p + 1]);
        }
    }

    // ---- precomputed phase-1 writer bases ----
    float2* pw0 = psh0 + (q * EPB) * HID + u;
    float2* pw1 = psh1 + (q * EPB) * HID + u;

    // ---- precomputed phase-2 task state ----
    // task0: q<7 -> (L0, e=q); q==7 -> (L1, e=0).  task1: q<6 -> (L1, e=q+1).
    const bool t0L1 = (q == 7);
    const int  e0   = t0L1 ? 0 : q;
    const float2* pr0 = (t0L1 ? psh1 : psh0) + e0 * HID + u;
    float*        hs0 = (t0L1 ? h2f : h1f) + e0 * HID + u;
    const float*  xb0 = xs + e0 * T_STEPS;
    const float4* bp0 = (t0L1 ? b1s : b0s) + u;
    const bool has1 = (q < 6);
    const int  e1   = has1 ? (q + 1) : 0;
    const float2* pr1 = psh1 + e1 * HID + u;
    float*        hs1 = h2f + e1 * HID + u;
    const float4* bp1 = b1s + u;
    const float4* xwp = xws + u;

    float cA = 0.0f, cB = 0.0f;
    __syncthreads();

#define Q (EPB * HID)   // 448: psh stride per q-slot (float2 units)

#pragma unroll 1
    for (int j = 0; j <= T_STEPS; ++j) {
        const int rb = j & 1;

        // ================= phase 1 =================
        if (j < T_STEPS) {     // layer0 partials for step j (reads h1[j-1])
            const ulonglong2* hp = (const ulonglong2*)(h1f + rb * Q) + s * 4;
#pragma unroll
            for (int e = 0; e < EPB; ++e) {
                ulonglong2 v0 = hp[e * 16 + 0], v1 = hp[e * 16 + 1];
                ulonglong2 v2 = hp[e * 16 + 2], v3 = hp[e * 16 + 3];
                u64 aA = 0, aB = 0;
                aA = fma2(v0.x, w0A[0], aA); aB = fma2(v0.x, w0B[0], aB);
                aA = fma2(v0.y, w0A[1], aA); aB = fma2(v0.y, w0B[1], aB);
                aA = fma2(v1.x, w0A[2], aA); aB = fma2(v1.x, w0B[2], aB);
                aA = fma2(v1.y, w0A[3], aA); aB = fma2(v1.y, w0B[3], aB);
                aA = fma2(v2.x, w0A[4], aA); aB = fma2(v2.x, w0B[4], aB);
                aA = fma2(v2.y, w0A[5], aA); aB = fma2(v2.y, w0B[5], aB);
                aA = fma2(v3.x, w0A[6], aA); aB = fma2(v3.x, w0B[6], aB);
                aA = fma2(v3.y, w0A[7], aA); aB = fma2(v3.y, w0B[7], aB);
                float2 fa = unpack2(aA), fb = unpack2(aB);
                pw0[e * HID] = make_float2(fa.x + fa.y, fb.x + fb.y);
            }
        }
        if (j > 0) {           // layer1 partials for step j-1 (reads h1[j-1], h2[j-2])
            const ulonglong2* hp = (s < 2)
                ? (const ulonglong2*)(h1f + rb * Q) + s * 8
                : (const ulonglong2*)(h2f + rb * Q) + (s - 2) * 8;
#pragma unroll
            for (int e = 0; e < EPB; ++e) {
                u64 aA = 0, aB = 0;
#pragma unroll
                for (int p = 0; p < 8; ++p) {
                    ulonglong2 v = hp[e * 16 + p];
                    aA = fma2(v.x, w1A[2 * p], aA);     aB = fma2(v.x, w1B[2 * p], aB);
                    aA = fma2(v.y, w1A[2 * p + 1], aA); aB = fma2(v.y, w1B[2 * p + 1], aB);
                }
                float2 fa = unpack2(aA), fb = unpack2(aB);
                pw1[e * HID] = make_float2(fa.x + fa.y, fb.x + fb.y);
            }
        }
        __syncthreads();

        // ================= phase 2 =================
        const int wo = (rb ^ 1) * Q;
        const bool act0 = t0L1 ? (j > 0) : (j < T_STEPS);
        if (act0) {
            float2 a0 = pr0[0 * Q], a1 = pr0[2 * Q], a2 = pr0[4 * Q], a3 = pr0[6 * Q];
            float2 g0 = pr0[1 * Q], g1 = pr0[3 * Q], g2 = pr0[5 * Q], g3 = pr0[7 * Q];
            float4 bb = *bp0;
            float pi = a0.x + a1.x + a2.x + a3.x + bb.x;
            float pf = a0.y + a1.y + a2.y + a3.y + bb.y;
            float pg = g0.x + g1.x + g2.x + g3.x + bb.z;
            float po = g0.y + g1.y + g2.y + g3.y + bb.w;
            if (!t0L1) {
                float xv = xb0[j];
                float4 xw = *xwp;
                pi += xv * xw.x; pf += xv * xw.y; pg += xv * xw.z; po += xv * xw.w;
            }
            float gi = sig_fast(pi), gf = sig_fast(pf);
            float gg = tanh_fast(pg), go = sig_fast(po);
            cA = gf * cA + gi * gg;
            hs0[wo] = go * tanh_fast(cA);
        }
        if (has1 && j > 0) {
            float2 a0 = pr1[0 * Q], a1 = pr1[2 * Q], a2 = pr1[4 * Q], a3 = pr1[6 * Q];
            float2 g0 = pr1[1 * Q], g1 = pr1[3 * Q], g2 = pr1[5 * Q], g3 = pr1[7 * Q];
            float4 bb = *bp1;
            float pi = a0.x + a1.x + a2.x + a3.x + bb.x;
            float pf = a0.y + a1.y + a2.y + a3.y + bb.y;
            float pg = g0.x + g1.x + g2.x + g3.x + bb.z;
            float po = g0.y + g1.y + g2.y + g3.y + bb.w;
            float gi = sig_fast(pi), gf = sig_fast(pf);
            float gg = tanh_fast(pg), go = sig_fast(po);
            cB = gf * cB + gi * gg;
            hs1[wo] = go * tanh_fast(cB);
        }
        __syncthreads();
    }

    // ---- final FC: h2[T-1] lives in slot 1 ----
    if (tid < EPB * 32) {
        const int e = tid >> 5, lane = tid & 31;
        const float* h2l = h2f + (1 * EPB + e) * HID;
        float acc = h2l[lane] * fcW[lane] + h2l[32 + lane] * fcW[32 + lane];
#pragma unroll
        for (int o = 16; o > 0; o >>= 1)
            acc += __shfl_down_sync(0xFFFFFFFFu, acc, o);
        if (lane == 0) {
            int be = b0e + e; if (be > B - 1) be = B - 1;
            out[be] = acc + fcb[0];
        }
    }
#undef Q
}

extern "C" void kernel_launch(void* const* d_in, const int* in_sizes, int n_in,
                              void* d_out, int out_size)
{
    const float* x    = (const float*)d_in[0];
    const float* Wih0 = (const float*)d_in[1];
    const float* Whh0 = (const float*)d_in[2];
    const float* bih0 = (const float*)d_in[3];
    const float* bhh0 = (const float*)d_in[4];
    const float* Wih1 = (const float*)d_in[5];
    const float* Whh1 = (const float*)d_in[6];
    const float* bih1 = (const float*)d_in[7];
    const float* bhh1 = (const float*)d_in[8];
    const float* fcW  = (const float*)d_in[9];
    const float* fcb  = (const float*)d_in[10];
    float* out = (float*)d_out;

    int B = in_sizes[0] / T_STEPS;
    if (B < 1) B = 1;
    int blocks = (B + EPB - 1) / EPB;

    const int smem_bytes = SMEM_FLOATS * 4;
    cudaFuncSetAttribute(lstm_fused, cudaFuncAttributeMaxDynamicSharedMemorySize,
                         smem_bytes);

    lstm_fused<<<blocks, NTHR, smem_bytes>>>(x, Wih0, Whh0, bih0, bhh0,
                                             Wih1, Whh1, bih1, bhh1,
                                             fcW, fcb, out, B);
}